// round 1
// baseline (speedup 1.0000x reference)
#include <cuda_runtime.h>
#include <math.h>

#define NN 10000
#define EE 640000
#define F  64
#define EFD 16

// ---- scratch (device globals; no allocations allowed) ----
__device__ float g_Asrc[NN*F];
__device__ float g_Adst[NN*F];
__device__ float g_Kn[NN*F];
__device__ float g_Qn[NN*F];
__device__ float g_emax[NN];
__device__ float g_denom[NN];
__device__ float g_hneigh[NN*F];
__device__ float g_e[EE];
__device__ float g_dist[EE];

__device__ __forceinline__ float siluf(float x) { return x / (1.f + __expf(-x)); }

__device__ __forceinline__ void atomicMaxF(float* addr, float v) {
    if (v >= 0.f) atomicMax((int*)addr, __float_as_int(v));
    else          atomicMin((unsigned int*)addr, (unsigned int)__float_as_int(v));
}

// ================= K0: per-node precompute + init =================
__global__ void k0_node_pre(const float* __restrict__ nf,
                            const float* __restrict__ We1,
                            const float* __restrict__ Wk,
                            const float* __restrict__ Wq) {
    __shared__ __align__(16) float srow[4 * F];
    int tid = threadIdx.x;
    int nodeBase = blockIdx.x * 4;
    srow[tid] = nf[(size_t)nodeBase * F + tid];
    __syncthreads();
    int ln = tid >> 6;
    int c  = tid & 63;
    int node = nodeBase + ln;
    const float* r = srow + ln * F;
    float a0 = 0.f, a1 = 0.f, a2 = 0.f, a3 = 0.f;
#pragma unroll 8
    for (int k = 0; k < F; ++k) {
        float x = r[k];
        a0 += x * __ldg(We1 + k * F + c);
        a1 += x * __ldg(We1 + (F + k) * F + c);
        a2 += x * __ldg(Wk  + k * F + c);
        a3 += x * __ldg(Wq  + k * F + c);
    }
    g_Asrc[node * F + c] = a0;
    g_Adst[node * F + c] = a1;
    g_Kn  [node * F + c] = a2;
    g_Qn  [node * F + c] = a3;
    g_hneigh[node * F + c] = 0.f;
    if (c == 0) { g_emax[node] = -3.402823466e38f; g_denom[node] = 0.f; }
}

// ================= K1: edge scores e = (msg_k . msg_q)/8, atomicMax =================
__global__ void k1_scores(const float* __restrict__ coord,
                          const float* __restrict__ efeat,
                          const float* __restrict__ Wk,
                          const int* __restrict__ src,
                          const int* __restrict__ dst) {
    __shared__ __align__(16) float sWke[EFD * F];   // rows 65..80 of W_k, [j][c]
    __shared__ __align__(16) float sWkd[F];         // row 64 of W_k
    int tid = threadIdx.x;
    for (int i = tid; i < EFD * F; i += 256) sWke[i] = Wk[65 * F + i];
    if (tid < F) sWkd[tid] = Wk[64 * F + tid];
    __syncthreads();

    int e = blockIdx.x * 256 + tid;
    if (e >= EE) return;
    int s = src[e], d = dst[e];

    float dx = coord[s * 3 + 0] - coord[d * 3 + 0];
    float dy = coord[s * 3 + 1] - coord[d * 3 + 1];
    float dz = coord[s * 3 + 2] - coord[d * 3 + 2];
    float dist = sqrtf(dx * dx + dy * dy + dz * dz);
    g_dist[e] = dist;

    const float4* efp = (const float4*)(efeat + (size_t)e * EFD);
    float4 e0 = __ldg(efp + 0), e1 = __ldg(efp + 1), e2 = __ldg(efp + 2), e3 = __ldg(efp + 3);
    float efv[16] = { e0.x,e0.y,e0.z,e0.w, e1.x,e1.y,e1.z,e1.w,
                      e2.x,e2.y,e2.z,e2.w, e3.x,e3.y,e3.z,e3.w };

    const float4* Ks = (const float4*)(g_Kn + (size_t)s * F);
    const float4* Qd = (const float4*)(g_Qn + (size_t)d * F);

    float acc = 0.f;
#pragma unroll 4
    for (int c4 = 0; c4 < 16; ++c4) {
        float4 kk = __ldg(Ks + c4);
        float4 qq = __ldg(Qd + c4);
        float4 wd = ((const float4*)sWkd)[c4];
        float mx = kk.x + dist * wd.x;
        float my = kk.y + dist * wd.y;
        float mz = kk.z + dist * wd.z;
        float mw = kk.w + dist * wd.w;
#pragma unroll
        for (int j = 0; j < 16; ++j) {
            float4 w = ((const float4*)(sWke + j * F))[c4];
            float ej = efv[j];
            mx += ej * w.x; my += ej * w.y; mz += ej * w.z; mw += ej * w.w;
        }
        acc += mx * qq.x + my * qq.y + mz * qq.z + mw * qq.w;
    }
    acc *= 0.125f;  // 1/sqrt(64)
    g_e[e] = acc;
    atomicMaxF(&g_emax[d], acc);
}

// ================= K2: softmax denominator =================
__global__ void k2_denom(const int* __restrict__ dst) {
    int e = blockIdx.x * 256 + threadIdx.x;
    if (e >= EE) return;
    int d = dst[e];
    float v = __expf(g_e[e] - g_emax[d]);
    atomicAdd(&g_denom[d], v);
}

// ================= K3: edge message MLP + attention scatter =================
__global__ void k3_message(const float* __restrict__ efeat,
                           const float* __restrict__ We1,
                           const float* __restrict__ be1,
                           const float* __restrict__ We2,
                           const float* __restrict__ be2,
                           const int* __restrict__ src,
                           const int* __restrict__ dst) {
    __shared__ __align__(16) float sWe2[F * F];      // [h][c]
    __shared__ __align__(16) float sWee1t[F * EFD];  // [h][j] transposed
    __shared__ __align__(16) float sW1d[F];
    __shared__ __align__(16) float sB1[F];
    __shared__ __align__(16) float sB2[F];
    int tid = threadIdx.x;
    for (int i = tid; i < F * F; i += 256) sWe2[i] = We2[i];
    for (int i = tid; i < F * EFD; i += 256) {
        int h = i / EFD, j = i % EFD;
        sWee1t[i] = We1[(129 + j) * F + h];
    }
    if (tid < F) { sW1d[tid] = We1[128 * F + tid]; sB1[tid] = be1[tid]; sB2[tid] = be2[tid]; }
    __syncthreads();

    int e = blockIdx.x * 256 + tid;
    if (e >= EE) return;
    int s = src[e], d = dst[e];
    float dist = g_dist[e];
    float att = __expf(g_e[e] - g_emax[d]) / g_denom[d];

    const float4* efp = (const float4*)(efeat + (size_t)e * EFD);
    float4 q0 = __ldg(efp + 0), q1 = __ldg(efp + 1), q2 = __ldg(efp + 2), q3 = __ldg(efp + 3);
    float efv[16] = { q0.x,q0.y,q0.z,q0.w, q1.x,q1.y,q1.z,q1.w,
                      q2.x,q2.y,q2.z,q2.w, q3.x,q3.y,q3.z,q3.w };

    const float4* As = (const float4*)(g_Asrc + (size_t)s * F);
    const float4* Ad = (const float4*)(g_Adst + (size_t)d * F);

    float4 acc[16];
#pragma unroll
    for (int c4 = 0; c4 < 16; ++c4) acc[c4] = ((const float4*)sB2)[c4];

#pragma unroll 2
    for (int h4 = 0; h4 < 16; ++h4) {
        float4 a  = __ldg(As + h4);
        float4 b  = __ldg(Ad + h4);
        float4 wd = ((const float4*)sW1d)[h4];
        float4 b1 = ((const float4*)sB1)[h4];
        float pre[4];
        pre[0] = a.x + b.x + dist * wd.x + b1.x;
        pre[1] = a.y + b.y + dist * wd.y + b1.y;
        pre[2] = a.z + b.z + dist * wd.z + b1.z;
        pre[3] = a.w + b.w + dist * wd.w + b1.w;
#pragma unroll
        for (int kk = 0; kk < 4; ++kk) {
            int h = h4 * 4 + kk;
            const float4* wt = (const float4*)(sWee1t + h * EFD);
            float4 w0 = wt[0], w1 = wt[1], w2 = wt[2], w3 = wt[3];
            float p = pre[kk]
                + efv[0]  * w0.x + efv[1]  * w0.y + efv[2]  * w0.z + efv[3]  * w0.w
                + efv[4]  * w1.x + efv[5]  * w1.y + efv[6]  * w1.z + efv[7]  * w1.w
                + efv[8]  * w2.x + efv[9]  * w2.y + efv[10] * w2.z + efv[11] * w2.w
                + efv[12] * w3.x + efv[13] * w3.y + efv[14] * w3.z + efv[15] * w3.w;
            float h1 = siluf(p);
            const float4* wr = (const float4*)(sWe2 + h * F);
#pragma unroll
            for (int c4 = 0; c4 < 16; ++c4) {
                float4 w = wr[c4];
                acc[c4].x += h1 * w.x;
                acc[c4].y += h1 * w.y;
                acc[c4].z += h1 * w.z;
                acc[c4].w += h1 * w.w;
            }
        }
    }

    float* outrow = g_hneigh + (size_t)d * F;
#pragma unroll
    for (int c4 = 0; c4 < 16; ++c4) {
        float4 v = acc[c4];
        float m0 = siluf(v.x) * att;
        float m1 = siluf(v.y) * att;
        float m2 = siluf(v.z) * att;
        float m3 = siluf(v.w) * att;
        atomicAdd(outrow + c4 * 4 + 0, m0);
        atomicAdd(outrow + c4 * 4 + 1, m1);
        atomicAdd(outrow + c4 * 4 + 2, m2);
        atomicAdd(outrow + c4 * 4 + 3, m3);
    }
}

// ================= K4: node MLP =================
__global__ void k4_node(const float* __restrict__ nf,
                        const float* __restrict__ Wn1,
                        const float* __restrict__ bn1,
                        const float* __restrict__ Wn2,
                        const float* __restrict__ bn2,
                        float* __restrict__ out) {
    __shared__ __align__(16) float sh1[4 * F];
    int tid = threadIdx.x;
    int ln = tid >> 6, c = tid & 63;
    int node = blockIdx.x * 4 + ln;

    const float4* nfr = (const float4*)(nf + (size_t)node * F);
    const float4* hr  = (const float4*)(g_hneigh + (size_t)node * F);

    float acc = bn1[c];
#pragma unroll 4
    for (int k4 = 0; k4 < 16; ++k4) {
        float4 x = __ldg(nfr + k4);
        acc += x.x * __ldg(Wn1 + (k4 * 4 + 0) * F + c);
        acc += x.y * __ldg(Wn1 + (k4 * 4 + 1) * F + c);
        acc += x.z * __ldg(Wn1 + (k4 * 4 + 2) * F + c);
        acc += x.w * __ldg(Wn1 + (k4 * 4 + 3) * F + c);
    }
#pragma unroll 4
    for (int k4 = 0; k4 < 16; ++k4) {
        float4 x = hr[k4];
        acc += x.x * __ldg(Wn1 + (F + k4 * 4 + 0) * F + c);
        acc += x.y * __ldg(Wn1 + (F + k4 * 4 + 1) * F + c);
        acc += x.z * __ldg(Wn1 + (F + k4 * 4 + 2) * F + c);
        acc += x.w * __ldg(Wn1 + (F + k4 * 4 + 3) * F + c);
    }
    sh1[ln * F + c] = siluf(acc);
    __syncthreads();

    const float* h1r = sh1 + ln * F;
    float o = bn2[c];
#pragma unroll 4
    for (int k4 = 0; k4 < 16; ++k4) {
        o += h1r[k4 * 4 + 0] * __ldg(Wn2 + (k4 * 4 + 0) * F + c);
        o += h1r[k4 * 4 + 1] * __ldg(Wn2 + (k4 * 4 + 1) * F + c);
        o += h1r[k4 * 4 + 2] * __ldg(Wn2 + (k4 * 4 + 2) * F + c);
        o += h1r[k4 * 4 + 3] * __ldg(Wn2 + (k4 * 4 + 3) * F + c);
    }
    out[(size_t)node * F + c] = o;
}

extern "C" void kernel_launch(void* const* d_in, const int* in_sizes, int n_in,
                              void* d_out, int out_size) {
    const float* nf    = (const float*)d_in[0];
    const float* coord = (const float*)d_in[1];
    const float* efeat = (const float*)d_in[2];
    const float* We1   = (const float*)d_in[3];
    const float* be1   = (const float*)d_in[4];
    const float* We2   = (const float*)d_in[5];
    const float* be2   = (const float*)d_in[6];
    const float* Wn1   = (const float*)d_in[7];
    const float* bn1   = (const float*)d_in[8];
    const float* Wn2   = (const float*)d_in[9];
    const float* bn2   = (const float*)d_in[10];
    const float* Wq    = (const float*)d_in[11];
    const float* Wk    = (const float*)d_in[12];
    const int*   src   = (const int*)d_in[13];
    const int*   dst   = (const int*)d_in[14];
    float* out = (float*)d_out;

    k0_node_pre<<<NN / 4, 256>>>(nf, We1, Wk, Wq);
    k1_scores<<<EE / 256, 256>>>(coord, efeat, Wk, src, dst);
    k2_denom<<<EE / 256, 256>>>(dst);
    k3_message<<<EE / 256, 256>>>(efeat, We1, be1, We2, be2, src, dst);
    k4_node<<<NN / 4, 256>>>(nf, Wn1, bn1, Wn2, bn2, out);
}

// round 2
// speedup vs baseline: 1.4318x; 1.4318x over previous
#include <cuda_runtime.h>
#include <math.h>

#define NN 10000
#define EE 640000
#define F  64
#define EFD 16

// ---- scratch (device globals; no allocations allowed) ----
__device__ float g_Asrc[NN*F];
__device__ float g_Adst[NN*F];
__device__ float g_Kn[NN*F];
__device__ float g_Qn[NN*F];
__device__ float g_Qk[NN*EFD];
__device__ float g_qd2[NN];
__device__ float g_emax[NN];
__device__ float g_denom[NN];
__device__ float g_hneigh[NN*F];
__device__ float g_e[EE];
__device__ float g_dist[EE];

__device__ __forceinline__ float siluf(float x) { return x / (1.f + __expf(-x)); }

__device__ __forceinline__ void atomicMaxF(float* addr, float v) {
    if (v >= 0.f) atomicMax((int*)addr, __float_as_int(v));
    else          atomicMin((unsigned int*)addr, (unsigned int)__float_as_int(v));
}

__device__ __forceinline__ void redAdd4(float* addr, float a, float b, float c, float d) {
    asm volatile("red.global.add.v4.f32 [%0], {%1,%2,%3,%4};"
                 :: "l"(addr), "f"(a), "f"(b), "f"(c), "f"(d) : "memory");
}

// ================= K0: per-node precompute + init =================
__global__ void k0_node_pre(const float* __restrict__ nf,
                            const float* __restrict__ We1,
                            const float* __restrict__ Wk,
                            const float* __restrict__ Wq) {
    __shared__ __align__(16) float srow[4 * F];
    __shared__ __align__(16) float sQ[4 * F];
    int tid = threadIdx.x;
    int nodeBase = blockIdx.x * 4;
    srow[tid] = nf[(size_t)nodeBase * F + tid];
    __syncthreads();
    int ln = tid >> 6;
    int c  = tid & 63;
    int node = nodeBase + ln;
    const float* r = srow + ln * F;
    float a0 = 0.f, a1 = 0.f, a2 = 0.f, a3 = 0.f;
#pragma unroll 8
    for (int k = 0; k < F; ++k) {
        float x = r[k];
        a0 += x * __ldg(We1 + k * F + c);
        a1 += x * __ldg(We1 + (F + k) * F + c);
        a2 += x * __ldg(Wk  + k * F + c);
        a3 += x * __ldg(Wq  + k * F + c);
    }
    g_Asrc[node * F + c] = a0;
    g_Adst[node * F + c] = a1;
    g_Kn  [node * F + c] = a2;
    g_Qn  [node * F + c] = a3;
    sQ[ln * F + c] = a3;
    g_hneigh[node * F + c] = 0.f;
    if (c == 0) { g_emax[node] = -3.402823466e38f; g_denom[node] = 0.f; }
    __syncthreads();
    // Qk[node][j] = sum_c Wke[j][c] * Qn[node][c]   (Wke = rows 65..80 of Wk)
    if (tid < 64) {
        int ln2 = tid >> 4, j = tid & 15;
        const float* q = sQ + ln2 * F;
        float acc = 0.f;
#pragma unroll 8
        for (int k = 0; k < F; ++k) acc += q[k] * __ldg(Wk + (65 + j) * F + k);
        g_Qk[(nodeBase + ln2) * EFD + j] = acc;
    } else if (tid < 68) {
        // qd2[node] = sum_c Wk[row 64][c] * Qn[node][c]
        int ln2 = tid - 64;
        const float* q = sQ + ln2 * F;
        float acc = 0.f;
#pragma unroll 8
        for (int k = 0; k < F; ++k) acc += q[k] * __ldg(Wk + 64 * F + k);
        g_qd2[nodeBase + ln2] = acc;
    }
}

// ================= K1: edge scores (fully factored) =================
__global__ void k1_scores(const float* __restrict__ coord,
                          const float* __restrict__ efeat,
                          const int* __restrict__ src,
                          const int* __restrict__ dst) {
    int e = blockIdx.x * 256 + threadIdx.x;
    if (e >= EE) return;
    int s = src[e], d = dst[e];

    float dx = coord[s * 3 + 0] - coord[d * 3 + 0];
    float dy = coord[s * 3 + 1] - coord[d * 3 + 1];
    float dz = coord[s * 3 + 2] - coord[d * 3 + 2];
    float dist = sqrtf(dx * dx + dy * dy + dz * dz);
    g_dist[e] = dist;

    const float4* Ks = (const float4*)(g_Kn + (size_t)s * F);
    const float4* Qd = (const float4*)(g_Qn + (size_t)d * F);
    float acc = 0.f;
#pragma unroll
    for (int i = 0; i < 16; ++i) {
        float4 a = __ldg(Ks + i), b = __ldg(Qd + i);
        acc += a.x * b.x + a.y * b.y + a.z * b.z + a.w * b.w;
    }
    acc += dist * __ldg(&g_qd2[d]);
    const float4* efp = (const float4*)(efeat + (size_t)e * EFD);
    const float4* qk  = (const float4*)(g_Qk + (size_t)d * EFD);
#pragma unroll
    for (int i = 0; i < 4; ++i) {
        float4 a = __ldg(efp + i), b = __ldg(qk + i);
        acc += a.x * b.x + a.y * b.y + a.z * b.z + a.w * b.w;
    }
    acc *= 0.125f;  // 1/sqrt(64)
    g_e[e] = acc;
    atomicMaxF(&g_emax[d], acc);
}

// ================= K2: softmax denominator =================
__global__ void k2_denom(const int* __restrict__ dst) {
    int e = blockIdx.x * 256 + threadIdx.x;
    if (e >= EE) return;
    int d = dst[e];
    float v = __expf(g_e[e] - g_emax[d]);
    atomicAdd(&g_denom[d], v);
}

// ================= K3: tiled edge-message GEMM + scatter =================
// Block = 256 threads, processes 256 edges.
// Phase A: each thread computes h1[0..63] of its edge -> sH1T[h][e] (transposed).
// Phase B: register-tiled GEMM OUT[256e x 64c] = H1 @ W_e2, thread tile 4e x 16c.
#define SM_H1   0            // 64*256 floats
#define SM_WE2  16384        // 64*64
#define SM_WEE1 20480        // 64*16 transposed [h][j]
#define SM_W1D  21504        // 64
#define SM_B1   21568        // 64
#define SM_B2   21632        // 64
#define SM_ATT  21696        // 256
#define SM_DST  21952        // 256 (ints)
#define SM_FLOATS 22208

__global__ void __launch_bounds__(256, 2)
k3_message(const float* __restrict__ efeat,
           const float* __restrict__ We1,
           const float* __restrict__ be1,
           const float* __restrict__ We2,
           const float* __restrict__ be2,
           const int* __restrict__ src,
           const int* __restrict__ dst) {
    extern __shared__ __align__(16) float sm[];
    float* sH1T   = sm + SM_H1;
    float* sWe2   = sm + SM_WE2;
    float* sWee1t = sm + SM_WEE1;
    float* sW1d   = sm + SM_W1D;
    float* sB1    = sm + SM_B1;
    float* sB2    = sm + SM_B2;
    float* sAtt   = sm + SM_ATT;
    int*   sDst   = (int*)(sm + SM_DST);

    int tid = threadIdx.x;
    for (int i = tid; i < F * F; i += 256) sWe2[i] = We2[i];
    for (int i = tid; i < F * EFD; i += 256) {
        int h = i / EFD, j = i % EFD;
        sWee1t[i] = We1[(129 + j) * F + h];
    }
    if (tid < F) { sW1d[tid] = We1[128 * F + tid]; sB1[tid] = be1[tid]; sB2[tid] = be2[tid]; }
    __syncthreads();

    // ---------------- Phase A ----------------
    int e = blockIdx.x * 256 + tid;
    {
        int s = src[e], d = dst[e];
        float dist = g_dist[e];
        float att = __expf(g_e[e] - g_emax[d]) / g_denom[d];
        sAtt[tid] = att;
        sDst[tid] = d;

        const float4* efp = (const float4*)(efeat + (size_t)e * EFD);
        float4 q0 = __ldg(efp + 0), q1 = __ldg(efp + 1), q2 = __ldg(efp + 2), q3 = __ldg(efp + 3);
        float efv[16] = { q0.x,q0.y,q0.z,q0.w, q1.x,q1.y,q1.z,q1.w,
                          q2.x,q2.y,q2.z,q2.w, q3.x,q3.y,q3.z,q3.w };

        const float4* As = (const float4*)(g_Asrc + (size_t)s * F);
        const float4* Ad = (const float4*)(g_Adst + (size_t)d * F);

#pragma unroll 4
        for (int h4 = 0; h4 < 16; ++h4) {
            float4 a  = __ldg(As + h4);
            float4 b  = __ldg(Ad + h4);
            float4 wd = ((const float4*)sW1d)[h4];
            float4 b1 = ((const float4*)sB1)[h4];
            float pre[4];
            pre[0] = a.x + b.x + dist * wd.x + b1.x;
            pre[1] = a.y + b.y + dist * wd.y + b1.y;
            pre[2] = a.z + b.z + dist * wd.z + b1.z;
            pre[3] = a.w + b.w + dist * wd.w + b1.w;
#pragma unroll
            for (int kk = 0; kk < 4; ++kk) {
                int h = h4 * 4 + kk;
                const float4* wt = (const float4*)(sWee1t + h * EFD);
                float4 w0 = wt[0], w1 = wt[1], w2 = wt[2], w3 = wt[3];
                float p = pre[kk]
                    + efv[0]  * w0.x + efv[1]  * w0.y + efv[2]  * w0.z + efv[3]  * w0.w
                    + efv[4]  * w1.x + efv[5]  * w1.y + efv[6]  * w1.z + efv[7]  * w1.w
                    + efv[8]  * w2.x + efv[9]  * w2.y + efv[10] * w2.z + efv[11] * w2.w
                    + efv[12] * w3.x + efv[13] * w3.y + efv[14] * w3.z + efv[15] * w3.w;
                sH1T[h * 256 + tid] = siluf(p);
            }
        }
    }
    __syncthreads();

    // ---------------- Phase B: GEMM 256e x 64c ----------------
    int et = tid & 63;   // edge tile: edges [et*4, et*4+4)
    int ct = tid >> 6;   // channel tile: channels [ct*16, ct*16+16)

    float4 acc0[4], acc1[4], acc2[4], acc3[4];  // [edge][c4]
#pragma unroll
    for (int i = 0; i < 4; ++i) {
        float4 b2 = ((const float4*)sB2)[ct * 4 + i];
        acc0[i] = b2; acc1[i] = b2; acc2[i] = b2; acc3[i] = b2;
    }

    const float* h1base = sH1T + et * 4;
    const float4* wbase = (const float4*)(sWe2 + ct * 16);
#pragma unroll 8
    for (int h = 0; h < F; ++h) {
        float4 h1 = *(const float4*)(h1base + h * 256);
        const float4* w = wbase + h * 16;
        float4 w0 = w[0], w1 = w[1], w2 = w[2], w3 = w[3];
        acc0[0].x += h1.x*w0.x; acc0[0].y += h1.x*w0.y; acc0[0].z += h1.x*w0.z; acc0[0].w += h1.x*w0.w;
        acc0[1].x += h1.x*w1.x; acc0[1].y += h1.x*w1.y; acc0[1].z += h1.x*w1.z; acc0[1].w += h1.x*w1.w;
        acc0[2].x += h1.x*w2.x; acc0[2].y += h1.x*w2.y; acc0[2].z += h1.x*w2.z; acc0[2].w += h1.x*w2.w;
        acc0[3].x += h1.x*w3.x; acc0[3].y += h1.x*w3.y; acc0[3].z += h1.x*w3.z; acc0[3].w += h1.x*w3.w;
        acc1[0].x += h1.y*w0.x; acc1[0].y += h1.y*w0.y; acc1[0].z += h1.y*w0.z; acc1[0].w += h1.y*w0.w;
        acc1[1].x += h1.y*w1.x; acc1[1].y += h1.y*w1.y; acc1[1].z += h1.y*w1.z; acc1[1].w += h1.y*w1.w;
        acc1[2].x += h1.y*w2.x; acc1[2].y += h1.y*w2.y; acc1[2].z += h1.y*w2.z; acc1[2].w += h1.y*w2.w;
        acc1[3].x += h1.y*w3.x; acc1[3].y += h1.y*w3.y; acc1[3].z += h1.y*w3.z; acc1[3].w += h1.y*w3.w;
        acc2[0].x += h1.z*w0.x; acc2[0].y += h1.z*w0.y; acc2[0].z += h1.z*w0.z; acc2[0].w += h1.z*w0.w;
        acc2[1].x += h1.z*w1.x; acc2[1].y += h1.z*w1.y; acc2[1].z += h1.z*w1.z; acc2[1].w += h1.z*w1.w;
        acc2[2].x += h1.z*w2.x; acc2[2].y += h1.z*w2.y; acc2[2].z += h1.z*w2.z; acc2[2].w += h1.z*w2.w;
        acc2[3].x += h1.z*w3.x; acc2[3].y += h1.z*w3.y; acc2[3].z += h1.z*w3.z; acc2[3].w += h1.z*w3.w;
        acc3[0].x += h1.w*w0.x; acc3[0].y += h1.w*w0.y; acc3[0].z += h1.w*w0.z; acc3[0].w += h1.w*w0.w;
        acc3[1].x += h1.w*w1.x; acc3[1].y += h1.w*w1.y; acc3[1].z += h1.w*w1.z; acc3[1].w += h1.w*w1.w;
        acc3[2].x += h1.w*w2.x; acc3[2].y += h1.w*w2.y; acc3[2].z += h1.w*w2.z; acc3[2].w += h1.w*w2.w;
        acc3[3].x += h1.w*w3.x; acc3[3].y += h1.w*w3.y; acc3[3].z += h1.w*w3.z; acc3[3].w += h1.w*w3.w;
    }

    // ---------------- Epilogue: silu * att, vector scatter ----------------
#pragma unroll
    for (int ee = 0; ee < 4; ++ee) {
        float4* accp = (ee == 0) ? acc0 : (ee == 1) ? acc1 : (ee == 2) ? acc2 : acc3;
        int el = et * 4 + ee;
        float att = sAtt[el];
        int d = sDst[el];
        float* outrow = g_hneigh + (size_t)d * F + ct * 16;
#pragma unroll
        for (int i = 0; i < 4; ++i) {
            float4 v = accp[i];
            redAdd4(outrow + i * 4,
                    siluf(v.x) * att, siluf(v.y) * att,
                    siluf(v.z) * att, siluf(v.w) * att);
        }
    }
}

// ================= K4: node MLP =================
__global__ void k4_node(const float* __restrict__ nf,
                        const float* __restrict__ Wn1,
                        const float* __restrict__ bn1,
                        const float* __restrict__ Wn2,
                        const float* __restrict__ bn2,
                        float* __restrict__ out) {
    __shared__ __align__(16) float sh1[4 * F];
    int tid = threadIdx.x;
    int ln = tid >> 6, c = tid & 63;
    int node = blockIdx.x * 4 + ln;

    const float4* nfr = (const float4*)(nf + (size_t)node * F);
    const float4* hr  = (const float4*)(g_hneigh + (size_t)node * F);

    float acc = bn1[c];
#pragma unroll 4
    for (int k4 = 0; k4 < 16; ++k4) {
        float4 x = __ldg(nfr + k4);
        acc += x.x * __ldg(Wn1 + (k4 * 4 + 0) * F + c);
        acc += x.y * __ldg(Wn1 + (k4 * 4 + 1) * F + c);
        acc += x.z * __ldg(Wn1 + (k4 * 4 + 2) * F + c);
        acc += x.w * __ldg(Wn1 + (k4 * 4 + 3) * F + c);
    }
#pragma unroll 4
    for (int k4 = 0; k4 < 16; ++k4) {
        float4 x = hr[k4];
        acc += x.x * __ldg(Wn1 + (F + k4 * 4 + 0) * F + c);
        acc += x.y * __ldg(Wn1 + (F + k4 * 4 + 1) * F + c);
        acc += x.z * __ldg(Wn1 + (F + k4 * 4 + 2) * F + c);
        acc += x.w * __ldg(Wn1 + (F + k4 * 4 + 3) * F + c);
    }
    sh1[ln * F + c] = siluf(acc);
    __syncthreads();

    const float* h1r = sh1 + ln * F;
    float o = bn2[c];
#pragma unroll 4
    for (int k4 = 0; k4 < 16; ++k4) {
        o += h1r[k4 * 4 + 0] * __ldg(Wn2 + (k4 * 4 + 0) * F + c);
        o += h1r[k4 * 4 + 1] * __ldg(Wn2 + (k4 * 4 + 1) * F + c);
        o += h1r[k4 * 4 + 2] * __ldg(Wn2 + (k4 * 4 + 2) * F + c);
        o += h1r[k4 * 4 + 3] * __ldg(Wn2 + (k4 * 4 + 3) * F + c);
    }
    out[(size_t)node * F + c] = o;
}

extern "C" void kernel_launch(void* const* d_in, const int* in_sizes, int n_in,
                              void* d_out, int out_size) {
    const float* nf    = (const float*)d_in[0];
    const float* coord = (const float*)d_in[1];
    const float* efeat = (const float*)d_in[2];
    const float* We1   = (const float*)d_in[3];
    const float* be1   = (const float*)d_in[4];
    const float* We2   = (const float*)d_in[5];
    const float* be2   = (const float*)d_in[6];
    const float* Wn1   = (const float*)d_in[7];
    const float* bn1   = (const float*)d_in[8];
    const float* Wn2   = (const float*)d_in[9];
    const float* bn2   = (const float*)d_in[10];
    const float* Wq    = (const float*)d_in[11];
    const float* Wk    = (const float*)d_in[12];
    const int*   src   = (const int*)d_in[13];
    const int*   dst   = (const int*)d_in[14];
    float* out = (float*)d_out;

    static int smem_set = 0;
    const int k3_smem = SM_FLOATS * (int)sizeof(float);
    if (!smem_set) {
        cudaFuncSetAttribute(k3_message, cudaFuncAttributeMaxDynamicSharedMemorySize, k3_smem);
        smem_set = 1;
    }

    k0_node_pre<<<NN / 4, 256>>>(nf, We1, Wk, Wq);
    k1_scores<<<EE / 256, 256>>>(coord, efeat, src, dst);
    k2_denom<<<EE / 256, 256>>>(dst);
    k3_message<<<EE / 256, 256, k3_smem>>>(efeat, We1, be1, We2, be2, src, dst);
    k4_node<<<NN / 4, 256>>>(nf, Wn1, bn1, Wn2, bn2, out);
}

// round 3
// speedup vs baseline: 1.4888x; 1.0398x over previous
#include <cuda_runtime.h>
#include <math.h>

#define NN 10000
#define EE 640000
#define F  64
#define EFD 16

typedef unsigned long long u64p;

// ---- scratch (device globals; no allocations allowed) ----
__device__ float g_Asrc[NN*F];
__device__ float g_Adst[NN*F];
__device__ float g_Kn[NN*F];
__device__ float g_Qn[NN*F];
__device__ float g_Qk[NN*EFD];
__device__ float g_qd2[NN];
__device__ float g_emax[NN];
__device__ float g_denom[NN];
__device__ float g_hneigh[NN*F];
__device__ float g_e[EE];
__device__ float g_dist[EE];

__device__ __forceinline__ float siluf(float x) { return x / (1.f + __expf(-x)); }

__device__ __forceinline__ void atomicMaxF(float* addr, float v) {
    if (v >= 0.f) atomicMax((int*)addr, __float_as_int(v));
    else          atomicMin((unsigned int*)addr, (unsigned int)__float_as_int(v));
}

__device__ __forceinline__ void redAdd4(float* addr, float a, float b, float c, float d) {
    asm volatile("red.global.add.v4.f32 [%0], {%1,%2,%3,%4};"
                 :: "l"(addr), "f"(a), "f"(b), "f"(c), "f"(d) : "memory");
}

__device__ __forceinline__ u64p pack2(float x, float y) {
    u64p r; asm("mov.b64 %0, {%1,%2};" : "=l"(r) : "f"(x), "f"(y)); return r;
}
__device__ __forceinline__ void unpack2(u64p v, float& x, float& y) {
    asm("mov.b64 {%0,%1}, %2;" : "=f"(x), "=f"(y) : "l"(v));
}
__device__ __forceinline__ void ffma2(u64p& d, u64p a, u64p b) {
    asm("fma.rn.f32x2 %0, %1, %2, %0;" : "+l"(d) : "l"(a), "l"(b));
}

// ================= K0: per-node precompute + init =================
__global__ void k0_node_pre(const float* __restrict__ nf,
                            const float* __restrict__ We1,
                            const float* __restrict__ Wk,
                            const float* __restrict__ Wq) {
    __shared__ __align__(16) float srow[4 * F];
    __shared__ __align__(16) float sQ[4 * F];
    int tid = threadIdx.x;
    int nodeBase = blockIdx.x * 4;
    srow[tid] = nf[(size_t)nodeBase * F + tid];
    __syncthreads();
    int ln = tid >> 6;
    int c  = tid & 63;
    int node = nodeBase + ln;
    const float* r = srow + ln * F;
    float a0 = 0.f, a1 = 0.f, a2 = 0.f, a3 = 0.f;
#pragma unroll 8
    for (int k = 0; k < F; ++k) {
        float x = r[k];
        a0 += x * __ldg(We1 + k * F + c);
        a1 += x * __ldg(We1 + (F + k) * F + c);
        a2 += x * __ldg(Wk  + k * F + c);
        a3 += x * __ldg(Wq  + k * F + c);
    }
    g_Asrc[node * F + c] = a0;
    g_Adst[node * F + c] = a1;
    g_Kn  [node * F + c] = a2;
    g_Qn  [node * F + c] = a3;
    sQ[ln * F + c] = a3;
    g_hneigh[node * F + c] = 0.f;
    if (c == 0) { g_emax[node] = -3.402823466e38f; g_denom[node] = 0.f; }
    __syncthreads();
    if (tid < 64) {
        int ln2 = tid >> 4, j = tid & 15;
        const float* q = sQ + ln2 * F;
        float acc = 0.f;
#pragma unroll 8
        for (int k = 0; k < F; ++k) acc += q[k] * __ldg(Wk + (65 + j) * F + k);
        g_Qk[(nodeBase + ln2) * EFD + j] = acc;
    } else if (tid < 68) {
        int ln2 = tid - 64;
        const float* q = sQ + ln2 * F;
        float acc = 0.f;
#pragma unroll 8
        for (int k = 0; k < F; ++k) acc += q[k] * __ldg(Wk + 64 * F + k);
        g_qd2[nodeBase + ln2] = acc;
    }
}

// ================= K1: edge scores (fully factored) =================
__global__ void k1_scores(const float* __restrict__ coord,
                          const float* __restrict__ efeat,
                          const int* __restrict__ src,
                          const int* __restrict__ dst) {
    int e = blockIdx.x * 256 + threadIdx.x;
    if (e >= EE) return;
    int s = src[e], d = dst[e];

    float dx = coord[s * 3 + 0] - coord[d * 3 + 0];
    float dy = coord[s * 3 + 1] - coord[d * 3 + 1];
    float dz = coord[s * 3 + 2] - coord[d * 3 + 2];
    float dist = sqrtf(dx * dx + dy * dy + dz * dz);
    g_dist[e] = dist;

    const float4* Ks = (const float4*)(g_Kn + (size_t)s * F);
    const float4* Qd = (const float4*)(g_Qn + (size_t)d * F);
    float acc = 0.f;
#pragma unroll
    for (int i = 0; i < 16; ++i) {
        float4 a = __ldg(Ks + i), b = __ldg(Qd + i);
        acc += a.x * b.x + a.y * b.y + a.z * b.z + a.w * b.w;
    }
    acc += dist * __ldg(&g_qd2[d]);
    const float4* efp = (const float4*)(efeat + (size_t)e * EFD);
    const float4* qk  = (const float4*)(g_Qk + (size_t)d * EFD);
#pragma unroll
    for (int i = 0; i < 4; ++i) {
        float4 a = __ldg(efp + i), b = __ldg(qk + i);
        acc += a.x * b.x + a.y * b.y + a.z * b.z + a.w * b.w;
    }
    acc *= 0.125f;
    g_e[e] = acc;
    atomicMaxF(&g_emax[d], acc);
}

// ================= K2: softmax denominator =================
__global__ void k2_denom(const int* __restrict__ dst) {
    int e = blockIdx.x * 256 + threadIdx.x;
    if (e >= EE) return;
    int d = dst[e];
    float v = __expf(g_e[e] - g_emax[d]);
    atomicAdd(&g_denom[d], v);
}

// ================= K3: tiled edge-message GEMM + scatter (FFMA2) =================
// Block = 256 threads, 128 edges.
// Phase A: 2 threads/edge, each computes 32 h values -> sH1T[h][e].
// Phase B: OUT[128e x 64c] = H1 @ W_e2, thread tile 2e x 16c, packed f32x2.
#define EPB 128              // edges per block
#define SM_H1   0            // 64*128
#define SM_WE2  8192         // 64*64
#define SM_WEE1 12288        // 64*16 transposed [h][j]
#define SM_W1D  13312        // 64
#define SM_B1   13376        // 64
#define SM_B2   13440        // 64
#define SM_ATT  13504        // 128
#define SM_DST  13632        // 128 (ints)
#define SM_FLOATS 13760

__global__ void __launch_bounds__(256, 3)
k3_message(const float* __restrict__ efeat,
           const float* __restrict__ We1,
           const float* __restrict__ be1,
           const float* __restrict__ We2,
           const float* __restrict__ be2,
           const int* __restrict__ src,
           const int* __restrict__ dst) {
    extern __shared__ __align__(16) float sm[];
    float* sH1T   = sm + SM_H1;
    float* sWe2   = sm + SM_WE2;
    float* sWee1t = sm + SM_WEE1;
    float* sW1d   = sm + SM_W1D;
    float* sB1    = sm + SM_B1;
    float* sB2    = sm + SM_B2;
    float* sAtt   = sm + SM_ATT;
    int*   sDst   = (int*)(sm + SM_DST);

    int tid = threadIdx.x;
    for (int i = tid; i < F * F; i += 256) sWe2[i] = We2[i];
    for (int i = tid; i < F * EFD; i += 256) {
        int h = i / EFD, j = i % EFD;
        sWee1t[i] = We1[(129 + j) * F + h];
    }
    if (tid < F) { sW1d[tid] = We1[128 * F + tid]; sB1[tid] = be1[tid]; sB2[tid] = be2[tid]; }
    __syncthreads();

    // ---------------- Phase A: h1 for 128 edges, 2 threads/edge ----------------
    {
        int etid = tid & 127;
        int half = tid >> 7;              // 0 -> h 0..31, 1 -> h 32..63
        int e = blockIdx.x * EPB + etid;
        int s = src[e], d = dst[e];
        float dist = g_dist[e];
        if (half == 0) {
            sAtt[etid] = __expf(g_e[e] - g_emax[d]) / g_denom[d];
            sDst[etid] = d;
        }

        const float4* efp = (const float4*)(efeat + (size_t)e * EFD);
        float4 q0 = __ldg(efp + 0), q1 = __ldg(efp + 1), q2 = __ldg(efp + 2), q3 = __ldg(efp + 3);
        u64p epk[8];
        epk[0] = pack2(q0.x, q0.y); epk[1] = pack2(q0.z, q0.w);
        epk[2] = pack2(q1.x, q1.y); epk[3] = pack2(q1.z, q1.w);
        epk[4] = pack2(q2.x, q2.y); epk[5] = pack2(q2.z, q2.w);
        epk[6] = pack2(q3.x, q3.y); epk[7] = pack2(q3.z, q3.w);

        const float4* As = (const float4*)(g_Asrc + (size_t)s * F);
        const float4* Ad = (const float4*)(g_Adst + (size_t)d * F);

#pragma unroll 2
        for (int g = 0; g < 8; ++g) {
            int h4 = half * 8 + g;
            float4 a  = __ldg(As + h4);
            float4 b  = __ldg(Ad + h4);
            float4 wd = ((const float4*)sW1d)[h4];
            float4 b1 = ((const float4*)sB1)[h4];
            float pre[4];
            pre[0] = a.x + b.x + dist * wd.x + b1.x;
            pre[1] = a.y + b.y + dist * wd.y + b1.y;
            pre[2] = a.z + b.z + dist * wd.z + b1.z;
            pre[3] = a.w + b.w + dist * wd.w + b1.w;
#pragma unroll
            for (int kk = 0; kk < 4; ++kk) {
                int h = h4 * 4 + kk;
                const u64p* wt = (const u64p*)(sWee1t + h * EFD);
                u64p acc2 = 0ULL;
#pragma unroll
                for (int j = 0; j < 8; ++j) ffma2(acc2, epk[j], wt[j]);
                float lo, hi; unpack2(acc2, lo, hi);
                sH1T[h * EPB + etid] = siluf(pre[kk] + lo + hi);
            }
        }
    }
    __syncthreads();

    // ---------------- Phase B: packed GEMM 128e x 64c ----------------
    int et = tid & 63;   // edges [et*2, et*2+2)
    int ct = tid >> 6;   // channels [ct*16, ct*16+16) as 8 f32x2 pairs

    u64p acc0[8], acc1[8];
    {
        const u64p* b2p = (const u64p*)sB2 + ct * 8;
#pragma unroll
        for (int i = 0; i < 8; ++i) { u64p v = b2p[i]; acc0[i] = v; acc1[i] = v; }
    }

    const float* h1base = sH1T + et * 2;
    const u64p* wrow = (const u64p*)sWe2 + ct * 8;
#pragma unroll 8
    for (int h = 0; h < F; ++h) {
        float2 h1 = *(const float2*)(h1base + h * EPB);
        u64p ha = pack2(h1.x, h1.x);
        u64p hb = pack2(h1.y, h1.y);
        const u64p* w = wrow + h * 32;
#pragma unroll
        for (int i = 0; i < 8; ++i) {
            u64p wv = w[i];
            ffma2(acc0[i], ha, wv);
            ffma2(acc1[i], hb, wv);
        }
    }

    // ---------------- Epilogue: silu * att, vector scatter ----------------
#pragma unroll
    for (int ee = 0; ee < 2; ++ee) {
        u64p* accp = ee ? acc1 : acc0;
        int el = et * 2 + ee;
        float att = sAtt[el];
        int d = sDst[el];
        float* outrow = g_hneigh + (size_t)d * F + ct * 16;
#pragma unroll
        for (int i = 0; i < 4; ++i) {
            float v0, v1, v2, v3;
            unpack2(accp[2 * i],     v0, v1);
            unpack2(accp[2 * i + 1], v2, v3);
            redAdd4(outrow + i * 4,
                    siluf(v0) * att, siluf(v1) * att,
                    siluf(v2) * att, siluf(v3) * att);
        }
    }
}

// ================= K4: node MLP =================
__global__ void k4_node(const float* __restrict__ nf,
                        const float* __restrict__ Wn1,
                        const float* __restrict__ bn1,
                        const float* __restrict__ Wn2,
                        const float* __restrict__ bn2,
                        float* __restrict__ out) {
    __shared__ __align__(16) float sh1[4 * F];
    int tid = threadIdx.x;
    int ln = tid >> 6, c = tid & 63;
    int node = blockIdx.x * 4 + ln;

    const float4* nfr = (const float4*)(nf + (size_t)node * F);
    const float4* hr  = (const float4*)(g_hneigh + (size_t)node * F);

    float acc = bn1[c];
#pragma unroll 4
    for (int k4 = 0; k4 < 16; ++k4) {
        float4 x = __ldg(nfr + k4);
        acc += x.x * __ldg(Wn1 + (k4 * 4 + 0) * F + c);
        acc += x.y * __ldg(Wn1 + (k4 * 4 + 1) * F + c);
        acc += x.z * __ldg(Wn1 + (k4 * 4 + 2) * F + c);
        acc += x.w * __ldg(Wn1 + (k4 * 4 + 3) * F + c);
    }
#pragma unroll 4
    for (int k4 = 0; k4 < 16; ++k4) {
        float4 x = hr[k4];
        acc += x.x * __ldg(Wn1 + (F + k4 * 4 + 0) * F + c);
        acc += x.y * __ldg(Wn1 + (F + k4 * 4 + 1) * F + c);
        acc += x.z * __ldg(Wn1 + (F + k4 * 4 + 2) * F + c);
        acc += x.w * __ldg(Wn1 + (F + k4 * 4 + 3) * F + c);
    }
    sh1[ln * F + c] = siluf(acc);
    __syncthreads();

    const float* h1r = sh1 + ln * F;
    float o = bn2[c];
#pragma unroll 4
    for (int k4 = 0; k4 < 16; ++k4) {
        o += h1r[k4 * 4 + 0] * __ldg(Wn2 + (k4 * 4 + 0) * F + c);
        o += h1r[k4 * 4 + 1] * __ldg(Wn2 + (k4 * 4 + 1) * F + c);
        o += h1r[k4 * 4 + 2] * __ldg(Wn2 + (k4 * 4 + 2) * F + c);
        o += h1r[k4 * 4 + 3] * __ldg(Wn2 + (k4 * 4 + 3) * F + c);
    }
    out[(size_t)node * F + c] = o;
}

extern "C" void kernel_launch(void* const* d_in, const int* in_sizes, int n_in,
                              void* d_out, int out_size) {
    const float* nf    = (const float*)d_in[0];
    const float* coord = (const float*)d_in[1];
    const float* efeat = (const float*)d_in[2];
    const float* We1   = (const float*)d_in[3];
    const float* be1   = (const float*)d_in[4];
    const float* We2   = (const float*)d_in[5];
    const float* be2   = (const float*)d_in[6];
    const float* Wn1   = (const float*)d_in[7];
    const float* bn1   = (const float*)d_in[8];
    const float* Wn2   = (const float*)d_in[9];
    const float* bn2   = (const float*)d_in[10];
    const float* Wq    = (const float*)d_in[11];
    const float* Wk    = (const float*)d_in[12];
    const int*   src   = (const int*)d_in[13];
    const int*   dst   = (const int*)d_in[14];
    float* out = (float*)d_out;

    static int smem_set = 0;
    const int k3_smem = SM_FLOATS * (int)sizeof(float);
    if (!smem_set) {
        cudaFuncSetAttribute(k3_message, cudaFuncAttributeMaxDynamicSharedMemorySize, k3_smem);
        smem_set = 1;
    }

    k0_node_pre<<<NN / 4, 256>>>(nf, We1, Wk, Wq);
    k1_scores<<<EE / 256, 256>>>(coord, efeat, src, dst);
    k2_denom<<<EE / 256, 256>>>(dst);
    k3_message<<<EE / EPB, 256, k3_smem>>>(efeat, We1, be1, We2, be2, src, dst);
    k4_node<<<NN / 4, 256>>>(nf, Wn1, bn1, Wn2, bn2, out);
}

// round 4
// speedup vs baseline: 1.5193x; 1.0205x over previous
#include <cuda_runtime.h>
#include <math.h>

#define NN 10000
#define EE 640000
#define F  64
#define EFD 16

typedef unsigned long long u64p;

// ---- scratch (device globals; no allocations allowed) ----
__device__ float g_Asrc[NN*F];
__device__ float g_Adst[NN*F];
__device__ float g_Kn[NN*F];
__device__ float g_Qn[NN*F];
__device__ float g_Qk[NN*EFD];
__device__ float g_qd2[NN];
__device__ float g_emax[NN];
__device__ float g_denom[NN];
__device__ float g_hneigh[NN*F];
__device__ float g_e[EE];
__device__ float g_dist[EE];

__device__ __forceinline__ float siluf(float x) { return x / (1.f + __expf(-x)); }

__device__ __forceinline__ void atomicMaxF(float* addr, float v) {
    if (v >= 0.f) atomicMax((int*)addr, __float_as_int(v));
    else          atomicMin((unsigned int*)addr, (unsigned int)__float_as_int(v));
}

__device__ __forceinline__ void redAdd4(float* addr, float a, float b, float c, float d) {
    asm volatile("red.global.add.v4.f32 [%0], {%1,%2,%3,%4};"
                 :: "l"(addr), "f"(a), "f"(b), "f"(c), "f"(d) : "memory");
}

__device__ __forceinline__ u64p pack2(float x, float y) {
    u64p r; asm("mov.b64 %0, {%1,%2};" : "=l"(r) : "f"(x), "f"(y)); return r;
}
__device__ __forceinline__ void unpack2(u64p v, float& x, float& y) {
    asm("mov.b64 {%0,%1}, %2;" : "=f"(x), "=f"(y) : "l"(v));
}
__device__ __forceinline__ void ffma2(u64p& d, u64p a, u64p b) {
    asm("fma.rn.f32x2 %0, %1, %2, %0;" : "+l"(d) : "l"(a), "l"(b));
}

// ================= K0: per-node precompute + init =================
__global__ void k0_node_pre(const float* __restrict__ nf,
                            const float* __restrict__ We1,
                            const float* __restrict__ Wk,
                            const float* __restrict__ Wq) {
    __shared__ __align__(16) float srow[4 * F];
    __shared__ __align__(16) float sQ[4 * F];
    int tid = threadIdx.x;
    int nodeBase = blockIdx.x * 4;
    srow[tid] = nf[(size_t)nodeBase * F + tid];
    __syncthreads();
    int ln = tid >> 6;
    int c  = tid & 63;
    int node = nodeBase + ln;
    const float* r = srow + ln * F;
    float a0 = 0.f, a1 = 0.f, a2 = 0.f, a3 = 0.f;
#pragma unroll 8
    for (int k = 0; k < F; ++k) {
        float x = r[k];
        a0 += x * __ldg(We1 + k * F + c);
        a1 += x * __ldg(We1 + (F + k) * F + c);
        a2 += x * __ldg(Wk  + k * F + c);
        a3 += x * __ldg(Wq  + k * F + c);
    }
    g_Asrc[node * F + c] = a0;
    g_Adst[node * F + c] = a1;
    g_Kn  [node * F + c] = a2;
    g_Qn  [node * F + c] = a3;
    sQ[ln * F + c] = a3;
    g_hneigh[node * F + c] = 0.f;
    if (c == 0) { g_emax[node] = -3.402823466e38f; g_denom[node] = 0.f; }
    __syncthreads();
    if (tid < 64) {
        int ln2 = tid >> 4, j = tid & 15;
        const float* q = sQ + ln2 * F;
        float acc = 0.f;
#pragma unroll 8
        for (int k = 0; k < F; ++k) acc += q[k] * __ldg(Wk + (65 + j) * F + k);
        g_Qk[(nodeBase + ln2) * EFD + j] = acc;
    } else if (tid < 68) {
        int ln2 = tid - 64;
        const float* q = sQ + ln2 * F;
        float acc = 0.f;
#pragma unroll 8
        for (int k = 0; k < F; ++k) acc += q[k] * __ldg(Wk + 64 * F + k);
        g_qd2[nodeBase + ln2] = acc;
    }
}

// ================= K1: edge scores (fully factored) =================
__global__ void k1_scores(const float* __restrict__ coord,
                          const float* __restrict__ efeat,
                          const int* __restrict__ src,
                          const int* __restrict__ dst) {
    int e = blockIdx.x * 256 + threadIdx.x;
    if (e >= EE) return;
    int s = src[e], d = dst[e];

    float dx = coord[s * 3 + 0] - coord[d * 3 + 0];
    float dy = coord[s * 3 + 1] - coord[d * 3 + 1];
    float dz = coord[s * 3 + 2] - coord[d * 3 + 2];
    float dist = sqrtf(dx * dx + dy * dy + dz * dz);
    g_dist[e] = dist;

    const float4* Ks = (const float4*)(g_Kn + (size_t)s * F);
    const float4* Qd = (const float4*)(g_Qn + (size_t)d * F);
    float acc = 0.f;
#pragma unroll
    for (int i = 0; i < 16; ++i) {
        float4 a = __ldg(Ks + i), b = __ldg(Qd + i);
        acc += a.x * b.x + a.y * b.y + a.z * b.z + a.w * b.w;
    }
    acc += dist * __ldg(&g_qd2[d]);
    const float4* efp = (const float4*)(efeat + (size_t)e * EFD);
    const float4* qk  = (const float4*)(g_Qk + (size_t)d * EFD);
#pragma unroll
    for (int i = 0; i < 4; ++i) {
        float4 a = __ldg(efp + i), b = __ldg(qk + i);
        acc += a.x * b.x + a.y * b.y + a.z * b.z + a.w * b.w;
    }
    acc *= 0.125f;
    g_e[e] = acc;
    atomicMaxF(&g_emax[d], acc);
}

// ================= K2: softmax denominator; g_e := exp(e - emax[d]) =================
__global__ void k2_denom(const int* __restrict__ dst) {
    int e = blockIdx.x * 256 + threadIdx.x;
    if (e >= EE) return;
    int d = dst[e];
    float v = __expf(g_e[e] - __ldg(&g_emax[d]));
    g_e[e] = v;
    atomicAdd(&g_denom[d], v);
}

// ================= K3: tiled edge-message GEMM + scatter (FFMA2, LDS.128) =================
// Block = 256 threads, 128 edges.
// Phase A: 2 threads/edge, each computes 32 h values -> sH1T[h][e].
// Phase B: OUT[128e x 64c] = H1 @ W_e2, thread tile 4e x 8c, packed f32x2, 128-bit LDS.
#define EPB 128              // edges per block
#define SM_H1   0            // 64*128
#define SM_WE2  8192         // 64*64
#define SM_WEE1 12288        // 64*16 transposed [h][j]
#define SM_W1D  13312        // 64
#define SM_B1   13376        // 64
#define SM_B2   13440        // 64
#define SM_ATT  13504        // 128
#define SM_DST  13632        // 128 (ints)
#define SM_FLOATS 13760

__global__ void __launch_bounds__(256, 3)
k3_message(const float* __restrict__ efeat,
           const float* __restrict__ We1,
           const float* __restrict__ be1,
           const float* __restrict__ We2,
           const float* __restrict__ be2,
           const int* __restrict__ src,
           const int* __restrict__ dst) {
    extern __shared__ __align__(16) float sm[];
    float* sH1T   = sm + SM_H1;
    float* sWe2   = sm + SM_WE2;
    float* sWee1t = sm + SM_WEE1;
    float* sW1d   = sm + SM_W1D;
    float* sB1    = sm + SM_B1;
    float* sB2    = sm + SM_B2;
    float* sAtt   = sm + SM_ATT;
    int*   sDst   = (int*)(sm + SM_DST);

    int tid = threadIdx.x;
    for (int i = tid; i < F * F; i += 256) sWe2[i] = We2[i];
    for (int i = tid; i < F * EFD; i += 256) {
        int h = i / EFD, j = i % EFD;
        sWee1t[i] = We1[(129 + j) * F + h];
    }
    if (tid < F) { sW1d[tid] = We1[128 * F + tid]; sB1[tid] = be1[tid]; sB2[tid] = be2[tid]; }
    __syncthreads();

    // ---------------- Phase A: h1 for 128 edges, 2 threads/edge ----------------
    {
        int etid = tid & 127;
        int half = tid >> 7;              // 0 -> h 0..31, 1 -> h 32..63
        int e = blockIdx.x * EPB + etid;
        int s = src[e], d = dst[e];
        float dist = g_dist[e];
        if (half == 0) {
            sAtt[etid] = __fdividef(g_e[e], g_denom[d]);   // g_e holds exp(e - emax)
            sDst[etid] = d;
        }

        const float4* efp = (const float4*)(efeat + (size_t)e * EFD);
        float4 q0 = __ldg(efp + 0), q1 = __ldg(efp + 1), q2 = __ldg(efp + 2), q3 = __ldg(efp + 3);
        u64p epk[8];
        epk[0] = pack2(q0.x, q0.y); epk[1] = pack2(q0.z, q0.w);
        epk[2] = pack2(q1.x, q1.y); epk[3] = pack2(q1.z, q1.w);
        epk[4] = pack2(q2.x, q2.y); epk[5] = pack2(q2.z, q2.w);
        epk[6] = pack2(q3.x, q3.y); epk[7] = pack2(q3.z, q3.w);

        const float4* As = (const float4*)(g_Asrc + (size_t)s * F);
        const float4* Ad = (const float4*)(g_Adst + (size_t)d * F);

#pragma unroll 2
        for (int g = 0; g < 8; ++g) {
            int h4 = half * 8 + g;
            float4 a  = __ldg(As + h4);
            float4 b  = __ldg(Ad + h4);
            float4 wd = ((const float4*)sW1d)[h4];
            float4 b1 = ((const float4*)sB1)[h4];
            float pre[4];
            pre[0] = a.x + b.x + dist * wd.x + b1.x;
            pre[1] = a.y + b.y + dist * wd.y + b1.y;
            pre[2] = a.z + b.z + dist * wd.z + b1.z;
            pre[3] = a.w + b.w + dist * wd.w + b1.w;
#pragma unroll
            for (int kk = 0; kk < 4; ++kk) {
                int h = h4 * 4 + kk;
                const ulonglong2* wt = (const ulonglong2*)(sWee1t + h * EFD);
                ulonglong2 wA = wt[0], wB = wt[1];
                u64p acc2 = 0ULL;
                ffma2(acc2, epk[0], wA.x); ffma2(acc2, epk[1], wA.y);
                ffma2(acc2, epk[2], wB.x); ffma2(acc2, epk[3], wB.y);
                ulonglong2 wC = wt[2], wD = wt[3];
                ffma2(acc2, epk[4], wC.x); ffma2(acc2, epk[5], wC.y);
                ffma2(acc2, epk[6], wD.x); ffma2(acc2, epk[7], wD.y);
                float lo, hi; unpack2(acc2, lo, hi);
                sH1T[h * EPB + etid] = siluf(pre[kk] + lo + hi);
            }
        }
    }
    __syncthreads();

    // ---------------- Phase B: packed GEMM 128e x 64c, tile 4e x 8c ----------------
    int et = tid & 31;   // edges [et*4, et*4+4)
    int ct = tid >> 5;   // channels [ct*8, ct*8+8) as 4 f32x2 pairs

    u64p acc[4][4];      // [edge][pair]
    {
        const ulonglong2* b2p = (const ulonglong2*)(sB2 + ct * 8);
        ulonglong2 bA = b2p[0], bB = b2p[1];
#pragma unroll
        for (int ee = 0; ee < 4; ++ee) {
            acc[ee][0] = bA.x; acc[ee][1] = bA.y;
            acc[ee][2] = bB.x; acc[ee][3] = bB.y;
        }
    }

    const float* h1base = sH1T + et * 4;
    const float* wbase  = sWe2 + ct * 8;
#pragma unroll 8
    for (int h = 0; h < F; ++h) {
        float4 h1 = *(const float4*)(h1base + h * EPB);
        const ulonglong2* w = (const ulonglong2*)(wbase + h * F);
        ulonglong2 wA = w[0], wB = w[1];
        u64p h0 = pack2(h1.x, h1.x);
        u64p h1p = pack2(h1.y, h1.y);
        u64p h2 = pack2(h1.z, h1.z);
        u64p h3 = pack2(h1.w, h1.w);
        ffma2(acc[0][0], h0, wA.x); ffma2(acc[0][1], h0, wA.y);
        ffma2(acc[0][2], h0, wB.x); ffma2(acc[0][3], h0, wB.y);
        ffma2(acc[1][0], h1p, wA.x); ffma2(acc[1][1], h1p, wA.y);
        ffma2(acc[1][2], h1p, wB.x); ffma2(acc[1][3], h1p, wB.y);
        ffma2(acc[2][0], h2, wA.x); ffma2(acc[2][1], h2, wA.y);
        ffma2(acc[2][2], h2, wB.x); ffma2(acc[2][3], h2, wB.y);
        ffma2(acc[3][0], h3, wA.x); ffma2(acc[3][1], h3, wA.y);
        ffma2(acc[3][2], h3, wB.x); ffma2(acc[3][3], h3, wB.y);
    }

    // ---------------- Epilogue: silu * att, vector scatter ----------------
#pragma unroll
    for (int ee = 0; ee < 4; ++ee) {
        int el = et * 4 + ee;
        float att = sAtt[el];
        int d = sDst[el];
        float* outrow = g_hneigh + (size_t)d * F + ct * 8;
        float v0, v1, v2, v3, v4, v5, v6, v7;
        unpack2(acc[ee][0], v0, v1);
        unpack2(acc[ee][1], v2, v3);
        unpack2(acc[ee][2], v4, v5);
        unpack2(acc[ee][3], v6, v7);
        redAdd4(outrow,     siluf(v0) * att, siluf(v1) * att, siluf(v2) * att, siluf(v3) * att);
        redAdd4(outrow + 4, siluf(v4) * att, siluf(v5) * att, siluf(v6) * att, siluf(v7) * att);
    }
}

// ================= K4: node MLP =================
__global__ void k4_node(const float* __restrict__ nf,
                        const float* __restrict__ Wn1,
                        const float* __restrict__ bn1,
                        const float* __restrict__ Wn2,
                        const float* __restrict__ bn2,
                        float* __restrict__ out) {
    __shared__ __align__(16) float sh1[4 * F];
    int tid = threadIdx.x;
    int ln = tid >> 6, c = tid & 63;
    int node = blockIdx.x * 4 + ln;

    const float4* nfr = (const float4*)(nf + (size_t)node * F);
    const float4* hr  = (const float4*)(g_hneigh + (size_t)node * F);

    float acc = bn1[c];
#pragma unroll 4
    for (int k4 = 0; k4 < 16; ++k4) {
        float4 x = __ldg(nfr + k4);
        acc += x.x * __ldg(Wn1 + (k4 * 4 + 0) * F + c);
        acc += x.y * __ldg(Wn1 + (k4 * 4 + 1) * F + c);
        acc += x.z * __ldg(Wn1 + (k4 * 4 + 2) * F + c);
        acc += x.w * __ldg(Wn1 + (k4 * 4 + 3) * F + c);
    }
#pragma unroll 4
    for (int k4 = 0; k4 < 16; ++k4) {
        float4 x = hr[k4];
        acc += x.x * __ldg(Wn1 + (F + k4 * 4 + 0) * F + c);
        acc += x.y * __ldg(Wn1 + (F + k4 * 4 + 1) * F + c);
        acc += x.z * __ldg(Wn1 + (F + k4 * 4 + 2) * F + c);
        acc += x.w * __ldg(Wn1 + (F + k4 * 4 + 3) * F + c);
    }
    sh1[ln * F + c] = siluf(acc);
    __syncthreads();

    const float* h1r = sh1 + ln * F;
    float o = bn2[c];
#pragma unroll 4
    for (int k4 = 0; k4 < 16; ++k4) {
        o += h1r[k4 * 4 + 0] * __ldg(Wn2 + (k4 * 4 + 0) * F + c);
        o += h1r[k4 * 4 + 1] * __ldg(Wn2 + (k4 * 4 + 1) * F + c);
        o += h1r[k4 * 4 + 2] * __ldg(Wn2 + (k4 * 4 + 2) * F + c);
        o += h1r[k4 * 4 + 3] * __ldg(Wn2 + (k4 * 4 + 3) * F + c);
    }
    out[(size_t)node * F + c] = o;
}

extern "C" void kernel_launch(void* const* d_in, const int* in_sizes, int n_in,
                              void* d_out, int out_size) {
    const float* nf    = (const float*)d_in[0];
    const float* coord = (const float*)d_in[1];
    const float* efeat = (const float*)d_in[2];
    const float* We1   = (const float*)d_in[3];
    const float* be1   = (const float*)d_in[4];
    const float* We2   = (const float*)d_in[5];
    const float* be2   = (const float*)d_in[6];
    const float* Wn1   = (const float*)d_in[7];
    const float* bn1   = (const float*)d_in[8];
    const float* Wn2   = (const float*)d_in[9];
    const float* bn2   = (const float*)d_in[10];
    const float* Wq    = (const float*)d_in[11];
    const float* Wk    = (const float*)d_in[12];
    const int*   src   = (const int*)d_in[13];
    const int*   dst   = (const int*)d_in[14];
    float* out = (float*)d_out;

    static int smem_set = 0;
    const int k3_smem = SM_FLOATS * (int)sizeof(float);
    if (!smem_set) {
        cudaFuncSetAttribute(k3_message, cudaFuncAttributeMaxDynamicSharedMemorySize, k3_smem);
        smem_set = 1;
    }

    k0_node_pre<<<NN / 4, 256>>>(nf, We1, Wk, Wq);
    k1_scores<<<EE / 256, 256>>>(coord, efeat, src, dst);
    k2_denom<<<EE / 256, 256>>>(dst);
    k3_message<<<EE / EPB, 256, k3_smem>>>(efeat, We1, be1, We2, be2, src, dst);
    k4_node<<<NN / 4, 256>>>(nf, Wn1, bn1, Wn2, bn2, out);
}

// round 5
// speedup vs baseline: 1.5824x; 1.0416x over previous
#include <cuda_runtime.h>
#include <math.h>

#define NN 10000
#define EE 640000
#define F  64
#define EFD 16

typedef unsigned long long u64p;

// ---- scratch (device globals; no allocations allowed) ----
__device__ float g_Asrc[NN*F];
__device__ float g_Adst[NN*F];
__device__ float g_Kn[NN*F];
__device__ float g_Qn[NN*F];
__device__ float g_Qk[NN*EFD];
__device__ float g_qd2[NN];
__device__ float g_emax[NN];
__device__ float g_denom[NN];
__device__ float g_hneigh[NN*F];
__device__ float g_e[EE];
__device__ float g_dist[EE];

__device__ __forceinline__ float siluf(float x) { return x / (1.f + __expf(-x)); }

__device__ __forceinline__ void atomicMaxF(float* addr, float v) {
    if (v >= 0.f) atomicMax((int*)addr, __float_as_int(v));
    else          atomicMin((unsigned int*)addr, (unsigned int)__float_as_int(v));
}

__device__ __forceinline__ void redAdd4(float* addr, float a, float b, float c, float d) {
    asm volatile("red.global.add.v4.f32 [%0], {%1,%2,%3,%4};"
                 :: "l"(addr), "f"(a), "f"(b), "f"(c), "f"(d) : "memory");
}

__device__ __forceinline__ u64p pack2(float x, float y) {
    u64p r; asm("mov.b64 %0, {%1,%2};" : "=l"(r) : "f"(x), "f"(y)); return r;
}
__device__ __forceinline__ void unpack2(u64p v, float& x, float& y) {
    asm("mov.b64 {%0,%1}, %2;" : "=f"(x), "=f"(y) : "l"(v));
}
__device__ __forceinline__ void ffma2(u64p& d, u64p a, u64p b) {
    asm("fma.rn.f32x2 %0, %1, %2, %0;" : "+l"(d) : "l"(a), "l"(b));
}

// ================= K0: per-node precompute + init =================
__global__ void k0_node_pre(const float* __restrict__ nf,
                            const float* __restrict__ We1,
                            const float* __restrict__ Wk,
                            const float* __restrict__ Wq) {
    __shared__ __align__(16) float srow[4 * F];
    __shared__ __align__(16) float sQ[4 * F];
    int tid = threadIdx.x;
    int nodeBase = blockIdx.x * 4;
    srow[tid] = nf[(size_t)nodeBase * F + tid];
    __syncthreads();
    int ln = tid >> 6;
    int c  = tid & 63;
    int node = nodeBase + ln;
    const float* r = srow + ln * F;
    float a0 = 0.f, a1 = 0.f, a2 = 0.f, a3 = 0.f;
#pragma unroll 8
    for (int k = 0; k < F; ++k) {
        float x = r[k];
        a0 += x * __ldg(We1 + k * F + c);
        a1 += x * __ldg(We1 + (F + k) * F + c);
        a2 += x * __ldg(Wk  + k * F + c);
        a3 += x * __ldg(Wq  + k * F + c);
    }
    g_Asrc[node * F + c] = a0;
    g_Adst[node * F + c] = a1;
    g_Kn  [node * F + c] = a2;
    g_Qn  [node * F + c] = a3;
    sQ[ln * F + c] = a3;
    g_hneigh[node * F + c] = 0.f;
    if (c == 0) { g_emax[node] = -3.402823466e38f; g_denom[node] = 0.f; }
    __syncthreads();
    if (tid < 64) {
        int ln2 = tid >> 4, j = tid & 15;
        const float* q = sQ + ln2 * F;
        float acc = 0.f;
#pragma unroll 8
        for (int k = 0; k < F; ++k) acc += q[k] * __ldg(Wk + (65 + j) * F + k);
        g_Qk[(nodeBase + ln2) * EFD + j] = acc;
    } else if (tid < 68) {
        int ln2 = tid - 64;
        const float* q = sQ + ln2 * F;
        float acc = 0.f;
#pragma unroll 8
        for (int k = 0; k < F; ++k) acc += q[k] * __ldg(Wk + 64 * F + k);
        g_qd2[nodeBase + ln2] = acc;
    }
}

// ================= K1: edge scores — warp-cooperative coalesced gather =================
// 16 lanes per edge: lane c holds float4 chunk c of Kn[s], Qn[d]; partial dots
// reduced via shfl within 16-lane groups. 2 edges per warp-iteration.
__global__ void __launch_bounds__(256)
k1_scores(const float* __restrict__ coord,
          const float* __restrict__ efeat,
          const int* __restrict__ src,
          const int* __restrict__ dst) {
    int tid = threadIdx.x;
    int warp = tid >> 5, lane = tid & 31;
    int sub = lane >> 4, c = lane & 15;
    int base = blockIdx.x * 128 + warp * 16;

#pragma unroll
    for (int it = 0; it < 8; ++it) {
        int e = base + it * 2 + sub;
        int s = __ldg(&src[e]);
        int d = __ldg(&dst[e]);

        float4 kv = __ldg((const float4*)(g_Kn + (size_t)s * F) + c);
        float4 qv = __ldg((const float4*)(g_Qn + (size_t)d * F) + c);
        float part = kv.x * qv.x + kv.y * qv.y + kv.z * qv.z + kv.w * qv.w;

        if (c < 4) {
            float4 ev = __ldg((const float4*)(efeat + (size_t)e * EFD) + c);
            float4 qk = __ldg((const float4*)(g_Qk + (size_t)d * EFD) + c);
            part += ev.x * qk.x + ev.y * qk.y + ev.z * qk.z + ev.w * qk.w;
        }

        float dist = 0.f;
        if (c == 0) {
            float dx = __ldg(&coord[s * 3 + 0]) - __ldg(&coord[d * 3 + 0]);
            float dy = __ldg(&coord[s * 3 + 1]) - __ldg(&coord[d * 3 + 1]);
            float dz = __ldg(&coord[s * 3 + 2]) - __ldg(&coord[d * 3 + 2]);
            dist = sqrtf(dx * dx + dy * dy + dz * dz);
            part += dist * __ldg(&g_qd2[d]);
        }

#pragma unroll
        for (int o = 8; o; o >>= 1)
            part += __shfl_down_sync(0xffffffffu, part, o, 16);

        if (c == 0) {
            float acc = part * 0.125f;
            g_e[e] = acc;
            g_dist[e] = dist;
            atomicMaxF(&g_emax[d], acc);
        }
    }
}

// ================= K2: softmax denominator; g_e := exp(e - emax[d]) =================
__global__ void k2_denom(const int* __restrict__ dst) {
    int e = blockIdx.x * 256 + threadIdx.x;
    if (e >= EE) return;
    int d = dst[e];
    float v = __expf(g_e[e] - __ldg(&g_emax[d]));
    g_e[e] = v;
    atomicAdd(&g_denom[d], v);
}

// ================= K3: staged edge-message GEMM + scatter =================
// Block = 256 threads, 128 edges.
// Stage 0: coalesced cooperative gather of Asrc[s]+Adst[d] sums + efeat into smem.
// Phase A: 2 threads/edge compute h1 -> sH1T[h][e] (FFMA2).
// Phase B: OUT[128e x 64c] = H1 @ W_e2, tile 4e x 8c, packed f32x2.
// Epilogue: stage silu*att into smem, then warp-coalesced red.global.add.v4.
#define EPB 128
#define SUMSTRIDE 68
#define EFSTRIDE  20
#define SM_SUM   0                       // 128*68 = 8704
#define SM_EF    8704                    // 128*20 = 2560
#define SM_H1    11264                   // 64*128 = 8192
#define SM_WE2   19456                   // 4096
#define SM_WEE1  23552                   // 1024
#define SM_W1D   24576                   // 64
#define SM_B1    24640                   // 64
#define SM_B2    24704                   // 64
#define SM_ATT   24768                   // 128
#define SM_DIST  24896                   // 128
#define SM_DSTI  25024                   // 128 ints
#define SM_SRCI  25152                   // 128 ints
#define SM_FLOATS 25280

__global__ void __launch_bounds__(256, 2)
k3_message(const float* __restrict__ efeat,
           const float* __restrict__ We1,
           const float* __restrict__ be1,
           const float* __restrict__ We2,
           const float* __restrict__ be2,
           const int* __restrict__ src,
           const int* __restrict__ dst) {
    extern __shared__ __align__(16) float sm[];
    float* sSum   = sm + SM_SUM;
    float* sEf    = sm + SM_EF;
    float* sH1T   = sm + SM_H1;
    float* sWe2   = sm + SM_WE2;
    float* sWee1t = sm + SM_WEE1;
    float* sW1d   = sm + SM_W1D;
    float* sB1    = sm + SM_B1;
    float* sB2    = sm + SM_B2;
    float* sAtt   = sm + SM_ATT;
    float* sDist  = sm + SM_DIST;
    int*   sDstA  = (int*)(sm + SM_DSTI);
    int*   sSrcA  = (int*)(sm + SM_SRCI);

    int tid = threadIdx.x;
    int blockbase = blockIdx.x * EPB;

    // ---- prestage: weights + per-edge scalars ----
    for (int i = tid; i < F * F; i += 256) sWe2[i] = We2[i];
    for (int i = tid; i < F * EFD; i += 256) {
        int h = i / EFD, j = i % EFD;
        sWee1t[i] = We1[(129 + j) * F + h];
    }
    if (tid < F) { sW1d[tid] = We1[128 * F + tid]; sB1[tid] = be1[tid]; sB2[tid] = be2[tid]; }
    if (tid < 128) {
        int e = blockbase + tid;
        int d = __ldg(&dst[e]);
        sDstA[tid] = d;
        sAtt[tid] = __fdividef(g_e[e], __ldg(&g_denom[d]));   // g_e holds exp(e - emax)
        sDist[tid] = g_dist[e];
    } else {
        int e = blockbase + tid - 128;
        sSrcA[tid - 128] = __ldg(&src[e]);
    }
    __syncthreads();

    // ---- stage 0: coalesced gather of Asrc[s]+Adst[d] into sSum ----
#pragma unroll
    for (int it = 0; it < 8; ++it) {
        int item = it * 256 + tid;   // 0..2047
        int e = item >> 4;
        int c = item & 15;
        int s = sSrcA[e];
        int d = sDstA[e];
        float4 a = __ldg((const float4*)(g_Asrc + (size_t)s * F) + c);
        float4 b = __ldg((const float4*)(g_Adst + (size_t)d * F) + c);
        *(float4*)(sSum + e * SUMSTRIDE + c * 4) =
            make_float4(a.x + b.x, a.y + b.y, a.z + b.z, a.w + b.w);
    }
    // ---- stage efeat (fully coalesced: consecutive edges contiguous) ----
#pragma unroll
    for (int it = 0; it < 2; ++it) {
        int item = it * 256 + tid;   // 0..511
        int e = item >> 2;
        int c = item & 3;
        float4 v = __ldg((const float4*)(efeat + (size_t)(blockbase + e) * EFD) + c);
        *(float4*)(sEf + e * EFSTRIDE + c * 4) = v;
    }
    __syncthreads();

    // ---------------- Phase A: h1 for 128 edges, 2 threads/edge ----------------
    {
        int etid = tid & 127;
        int half = tid >> 7;              // 0 -> h 0..31, 1 -> h 32..63
        float dist = sDist[etid];

        const float4* efp = (const float4*)(sEf + etid * EFSTRIDE);
        float4 q0 = efp[0], q1 = efp[1], q2 = efp[2], q3 = efp[3];
        u64p epk[8];
        epk[0] = pack2(q0.x, q0.y); epk[1] = pack2(q0.z, q0.w);
        epk[2] = pack2(q1.x, q1.y); epk[3] = pack2(q1.z, q1.w);
        epk[4] = pack2(q2.x, q2.y); epk[5] = pack2(q2.z, q2.w);
        epk[6] = pack2(q3.x, q3.y); epk[7] = pack2(q3.z, q3.w);

        const float4* sumr = (const float4*)(sSum + etid * SUMSTRIDE);

#pragma unroll 2
        for (int g = 0; g < 8; ++g) {
            int h4 = half * 8 + g;
            float4 ab = sumr[h4];
            float4 wd = ((const float4*)sW1d)[h4];
            float4 b1 = ((const float4*)sB1)[h4];
            float pre[4];
            pre[0] = ab.x + dist * wd.x + b1.x;
            pre[1] = ab.y + dist * wd.y + b1.y;
            pre[2] = ab.z + dist * wd.z + b1.z;
            pre[3] = ab.w + dist * wd.w + b1.w;
#pragma unroll
            for (int kk = 0; kk < 4; ++kk) {
                int h = h4 * 4 + kk;
                const ulonglong2* wt = (const ulonglong2*)(sWee1t + h * EFD);
                ulonglong2 wA = wt[0], wB = wt[1];
                u64p acc2 = 0ULL;
                ffma2(acc2, epk[0], wA.x); ffma2(acc2, epk[1], wA.y);
                ffma2(acc2, epk[2], wB.x); ffma2(acc2, epk[3], wB.y);
                ulonglong2 wC = wt[2], wD = wt[3];
                ffma2(acc2, epk[4], wC.x); ffma2(acc2, epk[5], wC.y);
                ffma2(acc2, epk[6], wD.x); ffma2(acc2, epk[7], wD.y);
                float lo, hi; unpack2(acc2, lo, hi);
                sH1T[h * EPB + etid] = siluf(pre[kk] + lo + hi);
            }
        }
    }
    __syncthreads();

    // ---------------- Phase B: packed GEMM 128e x 64c, tile 4e x 8c ----------------
    int et = tid & 31;   // edges [et*4, et*4+4)
    int ct = tid >> 5;   // channels [ct*8, ct*8+8)

    u64p acc[4][4];
    {
        const ulonglong2* b2p = (const ulonglong2*)(sB2 + ct * 8);
        ulonglong2 bA = b2p[0], bB = b2p[1];
#pragma unroll
        for (int ee = 0; ee < 4; ++ee) {
            acc[ee][0] = bA.x; acc[ee][1] = bA.y;
            acc[ee][2] = bB.x; acc[ee][3] = bB.y;
        }
    }

    const float* h1base = sH1T + et * 4;
    const float* wbase  = sWe2 + ct * 8;
#pragma unroll 8
    for (int h = 0; h < F; ++h) {
        float4 h1 = *(const float4*)(h1base + h * EPB);
        const ulonglong2* w = (const ulonglong2*)(wbase + h * F);
        ulonglong2 wA = w[0], wB = w[1];
        u64p h0 = pack2(h1.x, h1.x);
        u64p h1p = pack2(h1.y, h1.y);
        u64p h2 = pack2(h1.z, h1.z);
        u64p h3 = pack2(h1.w, h1.w);
        ffma2(acc[0][0], h0, wA.x); ffma2(acc[0][1], h0, wA.y);
        ffma2(acc[0][2], h0, wB.x); ffma2(acc[0][3], h0, wB.y);
        ffma2(acc[1][0], h1p, wA.x); ffma2(acc[1][1], h1p, wA.y);
        ffma2(acc[1][2], h1p, wB.x); ffma2(acc[1][3], h1p, wB.y);
        ffma2(acc[2][0], h2, wA.x); ffma2(acc[2][1], h2, wA.y);
        ffma2(acc[2][2], h2, wB.x); ffma2(acc[2][3], h2, wB.y);
        ffma2(acc[3][0], h3, wA.x); ffma2(acc[3][1], h3, wA.y);
        ffma2(acc[3][2], h3, wB.x); ffma2(acc[3][3], h3, wB.y);
    }

    // ---------------- Epilogue: stage silu*att into sSum (reused), coalesced REDG ----
#pragma unroll
    for (int ee = 0; ee < 4; ++ee) {
        int el = et * 4 + ee;
        float att = sAtt[el];
        float* orow = sSum + el * SUMSTRIDE + ct * 8;
        float v0, v1, v2, v3, v4, v5, v6, v7;
        unpack2(acc[ee][0], v0, v1);
        unpack2(acc[ee][1], v2, v3);
        unpack2(acc[ee][2], v4, v5);
        unpack2(acc[ee][3], v6, v7);
        *(float4*)(orow)     = make_float4(siluf(v0) * att, siluf(v1) * att,
                                           siluf(v2) * att, siluf(v3) * att);
        *(float4*)(orow + 4) = make_float4(siluf(v4) * att, siluf(v5) * att,
                                           siluf(v6) * att, siluf(v7) * att);
    }
    __syncthreads();

#pragma unroll
    for (int it = 0; it < 8; ++it) {
        int item = it * 256 + tid;   // 0..2047
        int e = item >> 4;
        int c = item & 15;
        float4 v = *(const float4*)(sSum + e * SUMSTRIDE + c * 4);
        redAdd4(g_hneigh + (size_t)sDstA[e] * F + c * 4, v.x, v.y, v.z, v.w);
    }
}

// ================= K4: node MLP =================
__global__ void k4_node(const float* __restrict__ nf,
                        const float* __restrict__ Wn1,
                        const float* __restrict__ bn1,
                        const float* __restrict__ Wn2,
                        const float* __restrict__ bn2,
                        float* __restrict__ out) {
    __shared__ __align__(16) float sh1[4 * F];
    int tid = threadIdx.x;
    int ln = tid >> 6, c = tid & 63;
    int node = blockIdx.x * 4 + ln;

    const float4* nfr = (const float4*)(nf + (size_t)node * F);
    const float4* hr  = (const float4*)(g_hneigh + (size_t)node * F);

    float acc = bn1[c];
#pragma unroll 4
    for (int k4 = 0; k4 < 16; ++k4) {
        float4 x = __ldg(nfr + k4);
        acc += x.x * __ldg(Wn1 + (k4 * 4 + 0) * F + c);
        acc += x.y * __ldg(Wn1 + (k4 * 4 + 1) * F + c);
        acc += x.z * __ldg(Wn1 + (k4 * 4 + 2) * F + c);
        acc += x.w * __ldg(Wn1 + (k4 * 4 + 3) * F + c);
    }
#pragma unroll 4
    for (int k4 = 0; k4 < 16; ++k4) {
        float4 x = hr[k4];
        acc += x.x * __ldg(Wn1 + (F + k4 * 4 + 0) * F + c);
        acc += x.y * __ldg(Wn1 + (F + k4 * 4 + 1) * F + c);
        acc += x.z * __ldg(Wn1 + (F + k4 * 4 + 2) * F + c);
        acc += x.w * __ldg(Wn1 + (F + k4 * 4 + 3) * F + c);
    }
    sh1[ln * F + c] = siluf(acc);
    __syncthreads();

    const float* h1r = sh1 + ln * F;
    float o = bn2[c];
#pragma unroll 4
    for (int k4 = 0; k4 < 16; ++k4) {
        o += h1r[k4 * 4 + 0] * __ldg(Wn2 + (k4 * 4 + 0) * F + c);
        o += h1r[k4 * 4 + 1] * __ldg(Wn2 + (k4 * 4 + 1) * F + c);
        o += h1r[k4 * 4 + 2] * __ldg(Wn2 + (k4 * 4 + 2) * F + c);
        o += h1r[k4 * 4 + 3] * __ldg(Wn2 + (k4 * 4 + 3) * F + c);
    }
    out[(size_t)node * F + c] = o;
}

extern "C" void kernel_launch(void* const* d_in, const int* in_sizes, int n_in,
                              void* d_out, int out_size) {
    const float* nf    = (const float*)d_in[0];
    const float* coord = (const float*)d_in[1];
    const float* efeat = (const float*)d_in[2];
    const float* We1   = (const float*)d_in[3];
    const float* be1   = (const float*)d_in[4];
    const float* We2   = (const float*)d_in[5];
    const float* be2   = (const float*)d_in[6];
    const float* Wn1   = (const float*)d_in[7];
    const float* bn1   = (const float*)d_in[8];
    const float* Wn2   = (const float*)d_in[9];
    const float* bn2   = (const float*)d_in[10];
    const float* Wq    = (const float*)d_in[11];
    const float* Wk    = (const float*)d_in[12];
    const int*   src   = (const int*)d_in[13];
    const int*   dst   = (const int*)d_in[14];
    float* out = (float*)d_out;

    static int smem_set = 0;
    const int k3_smem = SM_FLOATS * (int)sizeof(float);
    if (!smem_set) {
        cudaFuncSetAttribute(k3_message, cudaFuncAttributeMaxDynamicSharedMemorySize, k3_smem);
        smem_set = 1;
    }

    k0_node_pre<<<NN / 4, 256>>>(nf, We1, Wk, Wq);
    k1_scores<<<EE / 128, 256>>>(coord, efeat, src, dst);
    k2_denom<<<EE / 256, 256>>>(dst);
    k3_message<<<EE / EPB, 256, k3_smem>>>(efeat, We1, be1, We2, be2, src, dst);
    k4_node<<<NN / 4, 256>>>(nf, Wn1, bn1, Wn2, bn2, out);
}